// round 1
// baseline (speedup 1.0000x reference)
#include <cuda_runtime.h>
#include <cstdint>
#include <cstddef>

#define BB 2
#define HH 16
#define SS 2048
#define DD 128
#define TQ 64
#define TK 64
#define KTILES (SS / TK)
#define QSTRIDE 132   // 128 + 4 pad, keeps 16B alignment, 2-way LDS conflicts max
#define PSTRIDE 68    // 64 + 4 pad
#define SCALE 0.08838834764831845f

// per-row softmax stats scratch (B*H*S = 65536 rows)
__device__ float g_rowM[BB * HH * SS];
__device__ float g_rowL[BB * HH * SS];

union F2U { unsigned long long u; float2 f; };

__device__ __forceinline__ void ffma2(unsigned long long& d, unsigned long long a,
                                      unsigned long long b) {
    asm("fma.rn.f32x2 %0, %1, %2, %0;" : "+l"(d) : "l"(a), "l"(b));
}

__device__ __forceinline__ unsigned long long pack2(float lo, float hi) {
    F2U u; u.f = make_float2(lo, hi); return u.u;
}

// fast exp on the FMA pipe (avoids MUFU.EX2 which is only ~140G/s chip-wide).
// |rel err| ~1e-6 for x <= 0. Clamped so masked (-1e9) scores give ~0.
__device__ __forceinline__ float fexp(float x) {
    x = fmaxf(x, -87.0f);
    float y = x * 1.442695041f;            // log2(e)
    float t = y + 12582912.0f;             // 1.5*2^23 magic round-to-nearest
    int   n = __float_as_int(t) - 0x4B400000;
    float f = y - (t - 12582912.0f);       // f in [-0.5, 0.5]
    float p = 1.33335581e-3f;
    p = fmaf(p, f, 9.61812910e-3f);
    p = fmaf(p, f, 5.55041087e-2f);
    p = fmaf(p, f, 2.40226507e-1f);
    p = fmaf(p, f, 6.93147182e-1f);
    p = fmaf(p, f, 1.0f);
    return p * __int_as_float((n + 127) << 23);
}

// ---------------------------------------------------------------------------
// Kernel 1: raw scores (scale + bias + mask) -> attn buffer (as scratch),
// plus online per-row max / sum-of-exp into g_rowM / g_rowL.
// Grid: (S/TQ, B*H). Block: 256 = 16x16; thread tile: 4 q-rows x 4 k-cols.
// ---------------------------------------------------------------------------
__global__ __launch_bounds__(256) void k_scores(
    const float* __restrict__ q, const float* __restrict__ k,
    const int* __restrict__ mask, const float* __restrict__ bias,
    float* __restrict__ attn) {
    extern __shared__ float sm[];
    float* Qs = sm;                 // [TQ][QSTRIDE]
    float* Ks = sm + TQ * QSTRIDE;  // [TK][QSTRIDE]

    const int tid = threadIdx.x;
    const int tx = tid & 15, ty = tid >> 4;
    const int qt = blockIdx.x, bh = blockIdx.y;
    const int b = bh >> 4, h = bh & 15;

    const float* qb = q + ((size_t)bh * SS + (size_t)qt * TQ) * DD;
    const float* kb = k + (size_t)bh * SS * DD;
    float* ab = attn + ((size_t)bh * SS + (size_t)qt * TQ) * SS;
    const float* bb = bias + ((size_t)h * SS + (size_t)qt * TQ) * SS;
    const int* mb = mask + ((size_t)b * SS + (size_t)qt * TQ) * SS;

    // Load Q tile (row-major, coalesced float4)
    #pragma unroll
    for (int i = tid; i < TQ * (DD / 4); i += 256) {
        int r = i >> 5, c = (i & 31) << 2;
        *(float4*)(Qs + r * QSTRIDE + c) = *(const float4*)(qb + r * DD + c);
    }

    float m_run[4], l_run[4];
    #pragma unroll
    for (int i = 0; i < 4; i++) { m_run[i] = -3.0e38f; l_run[i] = 0.0f; }
    __syncthreads();

    for (int kt = 0; kt < KTILES; kt++) {
        // Load K tile
        #pragma unroll
        for (int i = tid; i < TK * (DD / 4); i += 256) {
            int r = i >> 5, c = (i & 31) << 2;
            *(float4*)(Ks + r * QSTRIDE + c) =
                *(const float4*)(kb + (size_t)(kt * TK + r) * DD + c);
        }
        __syncthreads();

        // acc2[i][j]: packed (even-d, odd-d) partial sums
        unsigned long long acc2[4][4];
        #pragma unroll
        for (int i = 0; i < 4; i++)
            #pragma unroll
            for (int j = 0; j < 4; j++) acc2[i][j] = 0ULL;

        #pragma unroll 4
        for (int d4 = 0; d4 < DD / 4; d4++) {
            ulonglong2 qv[4], kv[4];
            #pragma unroll
            for (int i = 0; i < 4; i++)
                qv[i] = *(const ulonglong2*)(Qs + (4 * ty + i) * QSTRIDE + d4 * 4);
            #pragma unroll
            for (int j = 0; j < 4; j++)
                kv[j] = *(const ulonglong2*)(Ks + (tx + 16 * j) * QSTRIDE + d4 * 4);
            #pragma unroll
            for (int i = 0; i < 4; i++)
                #pragma unroll
                for (int j = 0; j < 4; j++) {
                    ffma2(acc2[i][j], qv[i].x, kv[j].x);
                    ffma2(acc2[i][j], qv[i].y, kv[j].y);
                }
        }
        __syncthreads();  // Ks consumed; safe to overwrite next iter

        // Epilogue: scale + bias + mask, write raw scores, online max/sumexp
        #pragma unroll
        for (int i = 0; i < 4; i++) {
            int row = 4 * ty + i;
            const float* brow = bb + (size_t)row * SS + kt * TK;
            const int* mrow = mb + (size_t)row * SS + kt * TK;
            float* arow = ab + (size_t)row * SS + kt * TK;
            float sv[4];
            float mloc = -3.0e38f;
            #pragma unroll
            for (int j = 0; j < 4; j++) {
                int kc = tx + 16 * j;
                F2U u; u.u = acc2[i][j];
                float s = fmaf(u.f.x + u.f.y, SCALE, __ldg(brow + kc));
                if (__ldg(mrow + kc) == 0) s = -1.0e9f;
                arow[kc] = s;
                sv[j] = s;
                mloc = fmaxf(mloc, s);
            }
            #pragma unroll
            for (int o = 8; o > 0; o >>= 1)
                mloc = fmaxf(mloc, __shfl_xor_sync(0xffffffffu, mloc, o));
            float mnew = fmaxf(m_run[i], mloc);
            float sloc = 0.0f;
            #pragma unroll
            for (int j = 0; j < 4; j++) sloc += fexp(sv[j] - mnew);
            #pragma unroll
            for (int o = 8; o > 0; o >>= 1)
                sloc += __shfl_xor_sync(0xffffffffu, sloc, o);
            l_run[i] = l_run[i] * fexp(m_run[i] - mnew) + sloc;
            m_run[i] = mnew;
        }
    }

    if (tx == 0) {
        #pragma unroll
        for (int i = 0; i < 4; i++) {
            int row = qt * TQ + 4 * ty + i;
            g_rowM[(size_t)bh * SS + row] = m_run[i];
            g_rowL[(size_t)bh * SS + row] = l_run[i];
        }
    }
}

// ---------------------------------------------------------------------------
// Kernel 2: normalize attn in place (p = exp(s-m)/l), and out = P @ V.
// Grid: (S/TQ, B*H). Block 256; thread tile 4 rows x 8 d-cols (4tx & 64+4tx).
// ---------------------------------------------------------------------------
__global__ __launch_bounds__(256) void k_out(
    const float* __restrict__ v, float* __restrict__ attn,
    float* __restrict__ out) {
    extern __shared__ float sm[];
    float* Vs = sm;                  // [TK][QSTRIDE]
    float* Ps = sm + TK * QSTRIDE;   // [TQ][PSTRIDE]  (row-major: [row][kk])
    float* Ms = Ps + TQ * PSTRIDE;   // [64]
    float* Ls = Ms + 64;             // [64] (inverse l)

    const int tid = threadIdx.x;
    const int tx = tid & 15, ty = tid >> 4;
    const int qt = blockIdx.x, bh = blockIdx.y;

    const float* vb = v + (size_t)bh * SS * DD;
    float* ab = attn + ((size_t)bh * SS + (size_t)qt * TQ) * SS;
    float* ob = out + ((size_t)bh * SS + (size_t)qt * TQ) * DD;

    if (tid < 64) {
        int row = qt * TQ + tid;
        Ms[tid] = g_rowM[(size_t)bh * SS + row];
        Ls[tid] = 1.0f / g_rowL[(size_t)bh * SS + row];
    }

    unsigned long long acc2[4][4];
    #pragma unroll
    for (int i = 0; i < 4; i++)
        #pragma unroll
        for (int j = 0; j < 4; j++) acc2[i][j] = 0ULL;
    __syncthreads();

    for (int kt = 0; kt < KTILES; kt++) {
        // Load V tile
        #pragma unroll
        for (int i = tid; i < TK * (DD / 4); i += 256) {
            int r = i >> 5, c = (i & 31) << 2;
            *(float4*)(Vs + r * QSTRIDE + c) =
                *(const float4*)(vb + (size_t)(kt * TK + r) * DD + c);
        }
        // Normalize raw scores -> attn (in place) + stage into Ps
        #pragma unroll
        for (int i2 = tid; i2 < TQ * (TK / 4); i2 += 256) {
            int row = i2 >> 4, kc = (i2 & 15) << 2;
            float* ap = ab + (size_t)row * SS + kt * TK + kc;
            float4 s4 = *(float4*)ap;
            float m = Ms[row], il = Ls[row];
            s4.x = fexp(s4.x - m) * il;
            s4.y = fexp(s4.y - m) * il;
            s4.z = fexp(s4.z - m) * il;
            s4.w = fexp(s4.w - m) * il;
            *(float4*)ap = s4;
            *(float4*)(Ps + row * PSTRIDE + kc) = s4;
        }
        __syncthreads();

        // out tile += P(64x64) @ V(64x128)
        #pragma unroll 4
        for (int kk = 0; kk < TK; kk++) {
            ulonglong2 v0 = *(const ulonglong2*)(Vs + kk * QSTRIDE + 4 * tx);
            ulonglong2 v1 = *(const ulonglong2*)(Vs + kk * QSTRIDE + 64 + 4 * tx);
            #pragma unroll
            for (int i = 0; i < 4; i++) {
                float p = Ps[(4 * ty + i) * PSTRIDE + kk];
                unsigned long long pp = pack2(p, p);
                ffma2(acc2[i][0], pp, v0.x);
                ffma2(acc2[i][1], pp, v0.y);
                ffma2(acc2[i][2], pp, v1.x);
                ffma2(acc2[i][3], pp, v1.y);
            }
        }
        __syncthreads();
    }

    // Epilogue: write out
    #pragma unroll
    for (int i = 0; i < 4; i++) {
        int row = 4 * ty + i;
        F2U a0, a1, a2, a3;
        a0.u = acc2[i][0]; a1.u = acc2[i][1];
        a2.u = acc2[i][2]; a3.u = acc2[i][3];
        float4 o0 = make_float4(a0.f.x, a0.f.y, a1.f.x, a1.f.y);
        float4 o1 = make_float4(a2.f.x, a2.f.y, a3.f.x, a3.f.y);
        *(float4*)(ob + (size_t)row * DD + 4 * tx) = o0;
        *(float4*)(ob + (size_t)row * DD + 64 + 4 * tx) = o1;
    }
}

extern "C" void kernel_launch(void* const* d_in, const int* in_sizes, int n_in,
                              void* d_out, int out_size) {
    const float* q    = (const float*)d_in[0];
    const float* k    = (const float*)d_in[1];
    const float* v    = (const float*)d_in[2];
    const int*   mask = (const int*)d_in[3];
    const float* bias = (const float*)d_in[4];

    float* out  = (float*)d_out;
    float* attn = out + (size_t)BB * HH * SS * DD;  // outputs packed (out, attn)

    const int smem1 = 2 * TQ * QSTRIDE * 4;                         // 67584
    const int smem2 = (TK * QSTRIDE + TQ * PSTRIDE + 128) * 4;      // 51712
    cudaFuncSetAttribute(k_scores, cudaFuncAttributeMaxDynamicSharedMemorySize, smem1);
    cudaFuncSetAttribute(k_out,    cudaFuncAttributeMaxDynamicSharedMemorySize, smem2);

    dim3 grid(SS / TQ, BB * HH);
    k_scores<<<grid, 256, smem1>>>(q, k, mask, bias, attn);
    k_out<<<grid, 256, smem2>>>(v, attn, out);
}

// round 5
// speedup vs baseline: 1.3770x; 1.3770x over previous
#include <cuda_runtime.h>
#include <cstdint>
#include <cstddef>

#define BB 2
#define HH 16
#define SEQ 2048
#define HD 128
#define TS 128
#define NCH (SEQ / TS)
#define SCALE 0.08838834764831845f

// per-row softmax stats (B*H*S rows)
__device__ float g_rowM[BB * HH * SEQ];
__device__ float g_rowL[BB * HH * SEQ];

__device__ __forceinline__ float tf32r(float x) {  // round-to-nearest tf32
    uint32_t u; asm("cvt.rna.tf32.f32 %0, %1;" : "=r"(u) : "f"(x));
    return __uint_as_float(u);
}
__device__ __forceinline__ float4 t4(float4 v) {
    return make_float4(tf32r(v.x), tf32r(v.y), tf32r(v.z), tf32r(v.w));
}
// fast exp on fma/alu pipes, |rel err| ~1e-6 for x <= 0
__device__ __forceinline__ float fexp(float x) {
    x = fmaxf(x, -87.0f);
    float y = x * 1.442695041f;
    float t = y + 12582912.0f;
    int   n = __float_as_int(t) - 0x4B400000;
    float f = y - (t - 12582912.0f);
    float p = 1.33335581e-3f;
    p = fmaf(p, f, 9.61812910e-3f);
    p = fmaf(p, f, 5.55041087e-2f);
    p = fmaf(p, f, 2.40226507e-1f);
    p = fmaf(p, f, 6.93147182e-1f);
    p = fmaf(p, f, 1.0f);
    return p * __int_as_float((n + 127) << 23);
}

// m16n8k8 tf32 mma (sm_80+ PTX, works on compute_103 target)
__device__ __forceinline__ void mma8(float* c, const uint32_t* a, uint32_t b0, uint32_t b1) {
    asm volatile(
        "mma.sync.aligned.m16n8k8.row.col.f32.tf32.tf32.f32 "
        "{%0,%1,%2,%3}, {%4,%5,%6,%7}, {%8,%9}, {%0,%1,%2,%3};"
        : "+f"(c[0]), "+f"(c[1]), "+f"(c[2]), "+f"(c[3])
        : "r"(a[0]), "r"(a[1]), "r"(a[2]), "r"(a[3]), "r"(b0), "r"(b1));
}

#define STR 132   // stride (floats) for Q/K/P tiles: A/B frag loads conflict-free
#define VSTR 136  // stride for V tile: B frag loads conflict-free

// k1 smem float offsets
#define O_QS 0
#define O_KS (128 * STR)
#define O_MM (2 * 128 * STR)
#define O_LL (O_MM + 128)
#define O_PM (O_LL + 128)      // [2][128]
#define O_PSM (O_PM + 256)     // [2][128]
#define O_MN (O_PSM + 256)     // [128]
#define SMEM1 ((O_MN + 128) * 4)
// k2 smem float offsets
#define O_P2 0
#define O_VS (128 * STR)
#define O_M2 (O_VS + 128 * VSTR)
#define O_L2 (O_M2 + 128)
#define SMEM2 ((O_L2 + 128) * 4)

// ---------------------------------------------------------------------------
// k1: raw scores via tf32 mma.sync -> attn buffer (scratch); online (m,l).
// grid (16, 32), block 256 (8 warps as 4(M) x 2(N)); warp tile 32x64.
// ---------------------------------------------------------------------------
__global__ __launch_bounds__(256, 1) void k_scores(
    const float* __restrict__ q, const float* __restrict__ kmat,
    const int* __restrict__ mask, const float* __restrict__ bias,
    float* __restrict__ attn) {
    extern __shared__ float S[];
    uint32_t* SU = (uint32_t*)S;
    const int tid = threadIdx.x, w = tid >> 5, lane = tid & 31;
    const int qt = blockIdx.x, bh = blockIdx.y, b = bh >> 4, h = bh & 15;
    const int m32 = (w & 3) * 32, n64 = (w >> 2) * 64, nh = w >> 2;
    const int lg = lane >> 2, lm = lane & 3;

    const float* qb = q + ((size_t)bh * SEQ + (size_t)qt * TS) * HD;
    const float* kb = kmat + (size_t)bh * SEQ * HD;
    float* ab = attn + ((size_t)bh * SEQ + (size_t)qt * TS) * SEQ;
    const float* bb = bias + ((size_t)h * SEQ + (size_t)qt * TS) * SEQ;
    const int* mb = mask + ((size_t)b * SEQ + (size_t)qt * TS) * SEQ;

    // stage Q (whole kernel) + K chunk 0
    #pragma unroll
    for (int p = 0; p < 16; p++) {
        int idx = p * 1024 + tid * 4;
        int r = idx >> 7, c = idx & 127;
        *(float4*)(S + O_QS + r * STR + c) = t4(*(const float4*)(qb + idx));
        *(float4*)(S + O_KS + r * STR + c) = t4(*(const float4*)(kb + idx));
    }
    if (tid < 128) { S[O_MM + tid] = -3.0e38f; S[O_LL + tid] = 0.0f; }
    __syncthreads();

    for (int i = 0; i < NCH; i++) {
        float acc[2][8][4];
        #pragma unroll
        for (int mt = 0; mt < 2; mt++)
            #pragma unroll
            for (int nt = 0; nt < 8; nt++)
                #pragma unroll
                for (int j = 0; j < 4; j++) acc[mt][nt][j] = 0.0f;

        #pragma unroll 4
        for (int ks = 0; ks < 16; ks++) {
            const int kc = ks * 8;
            uint32_t a[2][4];
            #pragma unroll
            for (int mt = 0; mt < 2; mt++) {
                int r0 = m32 + mt * 16 + lg;
                a[mt][0] = SU[O_QS + r0 * STR + kc + lm];
                a[mt][1] = SU[O_QS + (r0 + 8) * STR + kc + lm];
                a[mt][2] = SU[O_QS + r0 * STR + kc + lm + 4];
                a[mt][3] = SU[O_QS + (r0 + 8) * STR + kc + lm + 4];
            }
            #pragma unroll
            for (int nt = 0; nt < 8; nt++) {
                int nr = n64 + nt * 8 + lg;
                uint32_t b0 = SU[O_KS + nr * STR + kc + lm];
                uint32_t b1 = SU[O_KS + nr * STR + kc + lm + 4];
                mma8(acc[0][nt], a[0], b0, b1);
                mma8(acc[1][nt], a[1], b0, b1);
            }
        }

        // epilogue-a: scale+bias+mask, write raw scores, per-colhalf row max
        float rmax[2][2] = {{-3.0e38f, -3.0e38f}, {-3.0e38f, -3.0e38f}};
        #pragma unroll
        for (int mt = 0; mt < 2; mt++)
            #pragma unroll
            for (int hh2 = 0; hh2 < 2; hh2++) {
                int r = m32 + mt * 16 + hh2 * 8 + lg;
                const size_t rb = (size_t)r * SEQ + (size_t)i * TS;
                #pragma unroll
                for (int nt = 0; nt < 8; nt++) {
                    int col = n64 + nt * 8 + 2 * lm;
                    float2 bv = *(const float2*)(bb + rb + col);
                    int2 mv = *(const int2*)(mb + rb + col);
                    float s0 = fmaf(acc[mt][nt][2 * hh2], SCALE, bv.x);
                    float s1 = fmaf(acc[mt][nt][2 * hh2 + 1], SCALE, bv.y);
                    if (mv.x == 0) s0 = -1.0e9f;
                    if (mv.y == 0) s1 = -1.0e9f;
                    *(float2*)(ab + rb + col) = make_float2(s0, s1);
                    acc[mt][nt][2 * hh2] = s0;
                    acc[mt][nt][2 * hh2 + 1] = s1;
                    rmax[mt][hh2] = fmaxf(rmax[mt][hh2], fmaxf(s0, s1));
                }
            }
        #pragma unroll
        for (int mt = 0; mt < 2; mt++)
            #pragma unroll
            for (int hh2 = 0; hh2 < 2; hh2++) {
                float m = rmax[mt][hh2];
                m = fmaxf(m, __shfl_xor_sync(0xffffffffu, m, 1));
                m = fmaxf(m, __shfl_xor_sync(0xffffffffu, m, 2));
                rmax[mt][hh2] = m;
            }
        if (lm == 0) {
            #pragma unroll
            for (int mt = 0; mt < 2; mt++)
                #pragma unroll
                for (int hh2 = 0; hh2 < 2; hh2++)
                    S[O_PM + nh * 128 + m32 + mt * 16 + hh2 * 8 + lg] = rmax[mt][hh2];
        }
        __syncthreads();

        // epilogue-b: per-row sum of exp (vs merged new max)
        #pragma unroll
        for (int mt = 0; mt < 2; mt++)
            #pragma unroll
            for (int hh2 = 0; hh2 < 2; hh2++) {
                int r = m32 + mt * 16 + hh2 * 8 + lg;
                float mn = fmaxf(S[O_MM + r],
                                 fmaxf(S[O_PM + r], S[O_PM + 128 + r]));
                float e = 0.0f;
                #pragma unroll
                for (int nt = 0; nt < 8; nt++)
                    e += fexp(acc[mt][nt][2 * hh2] - mn) +
                         fexp(acc[mt][nt][2 * hh2 + 1] - mn);
                e += __shfl_xor_sync(0xffffffffu, e, 1);
                e += __shfl_xor_sync(0xffffffffu, e, 2);
                if (lm == 0) {
                    S[O_PSM + nh * 128 + r] = e;
                    if (nh == 0) S[O_MN + r] = mn;
                }
            }
        // stage next K chunk (all warps past mma reads: sync above)
        if (i < NCH - 1) {
            const float* kc2 = kb + (size_t)(i + 1) * TS * HD;
            #pragma unroll
            for (int p = 0; p < 16; p++) {
                int idx = p * 1024 + tid * 4;
                int r = idx >> 7, c = idx & 127;
                *(float4*)(S + O_KS + r * STR + c) = t4(*(const float4*)(kc2 + idx));
            }
        }
        __syncthreads();
        // merge (runs concurrently with next chunk's mma; next sync orders it)
        if (tid < 128) {
            int r = tid;
            float mn = S[O_MN + r];
            S[O_LL + r] = S[O_LL + r] * fexp(S[O_MM + r] - mn) +
                          S[O_PSM + r] + S[O_PSM + 128 + r];
            S[O_MM + r] = mn;
        }
    }
    __syncthreads();
    if (tid < 128) {
        g_rowM[(size_t)bh * SEQ + qt * TS + tid] = S[O_MM + tid];
        g_rowL[(size_t)bh * SEQ + qt * TS + tid] = S[O_LL + tid];
    }
}

// ---------------------------------------------------------------------------
// k2: p = exp(s-m)/l -> final attn (in place); out = P @ V via tf32 mma.sync.
// V kept in natural [k][d] layout (stride 136) — .col B frag needs no transpose.
// ---------------------------------------------------------------------------
__global__ __launch_bounds__(256, 1) void k_out(
    const float* __restrict__ v, float* __restrict__ attn,
    float* __restrict__ out) {
    extern __shared__ float S[];
    uint32_t* SU = (uint32_t*)S;
    const int tid = threadIdx.x, w = tid >> 5, lane = tid & 31;
    const int qt = blockIdx.x, bh = blockIdx.y;
    const int m32 = (w & 3) * 32, n64 = (w >> 2) * 64;
    const int lg = lane >> 2, lm = lane & 3;

    const float* vb = v + (size_t)bh * SEQ * HD;
    float* ab = attn + ((size_t)bh * SEQ + (size_t)qt * TS) * SEQ;
    float* ob = out + ((size_t)bh * SEQ + (size_t)qt * TS) * HD;

    if (tid < 128) {
        S[O_M2 + tid] = g_rowM[(size_t)bh * SEQ + qt * TS + tid];
        S[O_L2 + tid] = 1.0f / g_rowL[(size_t)bh * SEQ + qt * TS + tid];
    }

    float acc[2][8][4];
    #pragma unroll
    for (int mt = 0; mt < 2; mt++)
        #pragma unroll
        for (int nt = 0; nt < 8; nt++)
            #pragma unroll
            for (int j = 0; j < 4; j++) acc[mt][nt][j] = 0.0f;
    __syncthreads();

    for (int i = 0; i < NCH; i++) {
        // stage P (normalize raw -> final attn, stash tf32) + V (natural layout)
        const float* vc = vb + (size_t)i * TS * HD;
        #pragma unroll
        for (int p = 0; p < 16; p++) {
            int idx = p * 1024 + tid * 4;
            int r = idx >> 7, c = idx & 127;
            float* ap = ab + (size_t)r * SEQ + (size_t)i * TS + c;
            float4 s4 = *(float4*)ap;
            float m = S[O_M2 + r], il = S[O_L2 + r];
            float4 p4 = make_float4(fexp(s4.x - m) * il, fexp(s4.y - m) * il,
                                    fexp(s4.z - m) * il, fexp(s4.w - m) * il);
            *(float4*)ap = p4;
            *(float4*)(S + O_P2 + r * STR + c) = t4(p4);
            *(float4*)(S + O_VS + r * VSTR + c) = t4(*(const float4*)(vc + idx));
        }
        __syncthreads();

        #pragma unroll 4
        for (int ks = 0; ks < 16; ks++) {
            const int kc = ks * 8;
            uint32_t a[2][4];
            #pragma unroll
            for (int mt = 0; mt < 2; mt++) {
                int r0 = m32 + mt * 16 + lg;
                a[mt][0] = SU[O_P2 + r0 * STR + kc + lm];
                a[mt][1] = SU[O_P2 + (r0 + 8) * STR + kc + lm];
                a[mt][2] = SU[O_P2 + r0 * STR + kc + lm + 4];
                a[mt][3] = SU[O_P2 + (r0 + 8) * STR + kc + lm + 4];
            }
            #pragma unroll
            for (int nt = 0; nt < 8; nt++) {
                int nc = n64 + nt * 8 + lg;
                uint32_t b0 = SU[O_VS + (kc + lm) * VSTR + nc];
                uint32_t b1 = SU[O_VS + (kc + lm + 4) * VSTR + nc];
                mma8(acc[0][nt], a[0], b0, b1);
                mma8(acc[1][nt], a[1], b0, b1);
            }
        }
        __syncthreads();
    }

    // epilogue: out tile from accumulators (float2 per fragment pair)
    #pragma unroll
    for (int mt = 0; mt < 2; mt++)
        #pragma unroll
        for (int hh2 = 0; hh2 < 2; hh2++) {
            int r = m32 + mt * 16 + hh2 * 8 + lg;
            #pragma unroll
            for (int nt = 0; nt < 8; nt++) {
                int col = n64 + nt * 8 + 2 * lm;
                *(float2*)(ob + (size_t)r * HD + col) =
                    make_float2(acc[mt][nt][2 * hh2], acc[mt][nt][2 * hh2 + 1]);
            }
        }
}

extern "C" void kernel_launch(void* const* d_in, const int* in_sizes, int n_in,
                              void* d_out, int out_size) {
    const float* q    = (const float*)d_in[0];
    const float* k    = (const float*)d_in[1];
    const float* v    = (const float*)d_in[2];
    const int*   mask = (const int*)d_in[3];
    const float* bias = (const float*)d_in[4];

    float* out  = (float*)d_out;
    float* attn = out + (size_t)BB * HH * SEQ * HD;

    cudaFuncSetAttribute(k_scores, cudaFuncAttributeMaxDynamicSharedMemorySize, SMEM1);
    cudaFuncSetAttribute(k_out,    cudaFuncAttributeMaxDynamicSharedMemorySize, SMEM2);

    dim3 grid(NCH, BB * HH);
    k_scores<<<grid, 256, SMEM1>>>(q, k, mask, bias, attn);
    k_out<<<grid, 256, SMEM2>>>(v, attn, out);
}